// round 5
// baseline (speedup 1.0000x reference)
#include <cuda_runtime.h>
#include <math.h>

#define B_ 4
#define A_ 16
#define N_ 8
#define L_ 512
#define DE_ 256
#define DH_ 64
#define H_ 8
#define DHEAD_ 32
#define NL_ 4096
#define LN_EPS 1e-5f

typedef unsigned long long u64;

// Scratch (no cudaMalloc allowed)
__device__ __align__(16) float g_qWw[B_*A_*H_*DE_];     // 512KB
__device__ float g_S0[B_*A_*H_];
__device__ float g_S1[B_*A_*H_];
__device__ __align__(16) float g_m[B_*H_*A_*DH_];       // 128KB

// ---- packed f32x2 helpers ----
__device__ __forceinline__ u64 pk2(float lo, float hi) {
    u64 r; asm("mov.b64 %0, {%1, %2};" : "=l"(r) : "f"(lo), "f"(hi)); return r;
}
__device__ __forceinline__ void upk2(u64 v, float& lo, float& hi) {
    asm("mov.b64 {%0, %1}, %2;" : "=f"(lo), "=f"(hi) : "l"(v));
}
__device__ __forceinline__ u64 fma2(u64 a, u64 b, u64 c) {
    u64 d; asm("fma.rn.f32x2 %0, %1, %2, %3;" : "=l"(d) : "l"(a), "l"(b), "l"(c)); return d;
}
__device__ __forceinline__ u64 add2(u64 a, u64 b) {
    u64 d; asm("add.rn.f32x2 %0, %1, %2;" : "=l"(d) : "l"(a), "l"(b)); return d;
}
__device__ __forceinline__ float upksum(u64 v) {
    float lo, hi; upk2(v, lo, hi); return lo + hi;
}
__device__ __forceinline__ float grp8_sum(float v) {
    v += __shfl_xor_sync(0xffffffffu, v, 1);
    v += __shfl_xor_sync(0xffffffffu, v, 2);
    v += __shfl_xor_sync(0xffffffffu, v, 4);
    return v;
}
__device__ __forceinline__ float warp_sum(float v) {
    #pragma unroll
    for (int o = 16; o > 0; o >>= 1) v += __shfl_xor_sync(0xffffffffu, v, o);
    return v;
}
__device__ __forceinline__ float warp_max(float v) {
    #pragma unroll
    for (int o = 16; o > 0; o >>= 1) v = fmaxf(v, __shfl_xor_sync(0xffffffffu, v, o));
    return v;
}

// ---------------------------------------------------------------- K0: zero
__global__ void k0_zero(float* __restrict__ out) {
    int i = blockIdx.x * blockDim.x + threadIdx.x;
    if (i < 256) out[i] = 0.f;
    if (i < B_*H_*A_*DH_) g_m[i] = 0.f;
    if (i < B_*A_*H_) { g_S0[i] = 0.f; g_S1[i] = 0.f; }
}

// ---------------------------------------------------------------- K12: q = LN(curr)@Wq.T, then qWw/S0/S1
__global__ void __launch_bounds__(256) k12_prep(
    const float* __restrict__ curr, const float* __restrict__ Wq,
    const float* __restrict__ Wk,
    const float* __restrict__ lqw, const float* __restrict__ lqb,
    const float* __restrict__ lkw, const float* __restrict__ lkb)
{
    int ba = blockIdx.x;          // 0..63
    int t  = threadIdx.x;         // 256
    int lane = t & 31;
    __shared__ __align__(16) float xs[DE_];
    __shared__ float red[256];
    __shared__ __align__(16) float qv[DE_];

    float x = curr[ba*DE_ + t];
    red[t] = x; __syncthreads();
    for (int s = 128; s > 0; s >>= 1) { if (t < s) red[t] += red[t+s]; __syncthreads(); }
    float mu = red[0] * (1.f/DE_);
    __syncthreads();
    red[t] = (x-mu)*(x-mu); __syncthreads();
    for (int s = 128; s > 0; s >>= 1) { if (t < s) red[t] += red[t+s]; __syncthreads(); }
    float rsd = rsqrtf(red[0] * (1.f/DE_) + LN_EPS);
    __syncthreads();
    xs[t] = (x - mu) * rsd * lqw[t] + lqb[t];
    __syncthreads();

    float acc = 0.f;
    const float* wr = Wq + t*DE_;
    #pragma unroll 8
    for (int i = 0; i < DE_; i += 4) {
        float4 xv = *(const float4*)(xs + i);
        float4 wv = *(const float4*)(wr + i);
        acc += xv.x*wv.x + xv.y*wv.y + xv.z*wv.z + xv.w*wv.w;
    }
    qv[t] = acc;
    __syncthreads();

    const float sc = 0.1767766952966369f;   // 1/sqrt(32)
    float wkt = lkw[t], bkt = lkb[t];
    #pragma unroll 1
    for (int h = 0; h < H_; h++) {
        float a2 = 0.f;
        #pragma unroll 8
        for (int d = 0; d < DHEAD_; d++)
            a2 += qv[h*DHEAD_ + d] * Wk[(h*DHEAD_ + d)*DE_ + t];
        float qww = a2 * wkt * sc;
        float s0c = a2 * bkt * sc;
        g_qWw[(size_t)(ba*H_ + h)*DE_ + t] = qww;
        float r1 = warp_sum(qww);
        float r0 = warp_sum(s0c);
        if (lane == 0) {
            atomicAdd(&g_S1[ba*H_+h], r1);
            atomicAdd(&g_S0[ba*H_+h], r0);
        }
    }
}

// ---------------------------------------------------------------- K3: fused LN+proj scores
// G=8 lanes/row, 2 rows per lane-group, 8 rows/warp/pass.
// i-loop in 4 batches of 2 (bounded live set -> no spills, good occupancy).
__global__ void __launch_bounds__(256) k3_scores(
    const float* __restrict__ demo, const int* __restrict__ mask,
    float* __restrict__ attn)
{
    int ba    = blockIdx.y;               // 64
    int chunk = blockIdx.x;               // 16 chunks of 256 rows
    int b = ba >> 4, a = ba & 15;
    int t = threadIdx.x;
    int warp = t >> 5, lane = t & 31;
    int g  = lane & 7;                    // element-slice within row
    int r4 = lane >> 3;                   // row-group 0..3

    __shared__ __align__(16) float4 cs[H_][DE_/4];   // 8KB coefficients
    __shared__ float S0s[H_], S1s[H_];

    for (int k = t; k < H_*DE_/4; k += 256) {
        int h = k >> 6, i4 = k & 63;
        cs[h][i4] = ((const float4*)(g_qWw + (size_t)(ba*H_ + h)*DE_))[i4];
    }
    if (t < H_) { S1s[t] = g_S1[ba*H_+t]; S0s[t] = g_S0[ba*H_+t]; }
    __syncthreads();

    int base = chunk*256 + warp*32;
    #pragma unroll 1
    for (int pass = 0; pass < 4; pass++) {
        int xr0 = base + pass*8 + r4*2;
        int xr1 = xr0 + 1;
        const float4* p0 = (const float4*)(demo + ((size_t)(b*NL_ + xr0)*A_ + a)*DE_);
        const float4* p1 = p0 + (A_*DE_/4);

        u64 sum0 = 0, ssq0 = 0, sum1 = 0, ssq1 = 0;
        u64 dot0[H_], dot1[H_];
        #pragma unroll
        for (int h = 0; h < H_; h++) { dot0[h] = 0; dot1[h] = 0; }

        #pragma unroll 2
        for (int ib = 0; ib < 4; ib++) {
            // batch of 2 i-steps: 4 live float4 loads
            float4 xa0 = __ldcs(p0 + (2*ib+0)*8 + g);
            float4 xb0 = __ldcs(p1 + (2*ib+0)*8 + g);
            float4 xa1 = __ldcs(p0 + (2*ib+1)*8 + g);
            float4 xb1 = __ldcs(p1 + (2*ib+1)*8 + g);

            u64 a00 = pk2(xa0.x, xa0.y), a01 = pk2(xa0.z, xa0.w);
            u64 b00 = pk2(xb0.x, xb0.y), b01 = pk2(xb0.z, xb0.w);
            u64 a10 = pk2(xa1.x, xa1.y), a11 = pk2(xa1.z, xa1.w);
            u64 b10 = pk2(xb1.x, xb1.y), b11 = pk2(xb1.z, xb1.w);

            sum0 = add2(sum0, a00); sum0 = add2(sum0, a01);
            sum0 = add2(sum0, a10); sum0 = add2(sum0, a11);
            ssq0 = fma2(a00, a00, ssq0); ssq0 = fma2(a01, a01, ssq0);
            ssq0 = fma2(a10, a10, ssq0); ssq0 = fma2(a11, a11, ssq0);
            sum1 = add2(sum1, b00); sum1 = add2(sum1, b01);
            sum1 = add2(sum1, b10); sum1 = add2(sum1, b11);
            ssq1 = fma2(b00, b00, ssq1); ssq1 = fma2(b01, b01, ssq1);
            ssq1 = fma2(b10, b10, ssq1); ssq1 = fma2(b11, b11, ssq1);

            #pragma unroll
            for (int h = 0; h < H_; h++) {
                float4 cv0 = cs[h][(2*ib+0)*8 + g];
                u64 c00 = pk2(cv0.x, cv0.y), c01 = pk2(cv0.z, cv0.w);
                dot0[h] = fma2(c00, a00, dot0[h]); dot0[h] = fma2(c01, a01, dot0[h]);
                dot1[h] = fma2(c00, b00, dot1[h]); dot1[h] = fma2(c01, b01, dot1[h]);
                float4 cv1 = cs[h][(2*ib+1)*8 + g];
                u64 c10 = pk2(cv1.x, cv1.y), c11 = pk2(cv1.z, cv1.w);
                dot0[h] = fma2(c10, a10, dot0[h]); dot0[h] = fma2(c11, a11, dot0[h]);
                dot1[h] = fma2(c10, b10, dot1[h]); dot1[h] = fma2(c11, b11, dot1[h]);
            }
        }

        float s0 = grp8_sum(upksum(sum0));
        float q0 = grp8_sum(upksum(ssq0));
        float s1 = grp8_sum(upksum(sum1));
        float q1 = grp8_sum(upksum(ssq1));
        float d0[H_], d1[H_];
        #pragma unroll
        for (int h = 0; h < H_; h++) {
            d0[h] = grp8_sum(upksum(dot0[h]));
            d1[h] = grp8_sum(upksum(dot1[h]));
        }

        float mu0  = s0 * (1.f/256.f);
        float rsd0 = rsqrtf(q0 * (1.f/256.f) - mu0*mu0 + LN_EPS);
        float mu1  = s1 * (1.f/256.f);
        float rsd1 = rsqrtf(q1 * (1.f/256.f) - mu1*mu1 + LN_EPS);
        int mk0 = mask[b*NL_ + xr0];
        int mk1 = mask[b*NL_ + xr1];

        #pragma unroll
        for (int h = 0; h < H_; h++) {
            if (g == h) {
                float sc0 = (d0[h] - mu0*S1s[h]) * rsd0 + S0s[h];
                float sc1 = (d1[h] - mu1*S1s[h]) * rsd1 + S0s[h];
                size_t rb = ((size_t)(b*H_+h)*A_ + a)*NL_;
                attn[rb + xr0] = mk0 ? sc0 : -INFINITY;
                attn[rb + xr1] = mk1 ? sc1 : -INFINITY;
            }
        }
    }
}

// ---------------------------------------------------------------- K4: softmax in-place (shuffle-based)
__global__ void __launch_bounds__(256) k4_softmax(float* __restrict__ attn)
{
    int row = blockIdx.x;                 // 512 = b*H*A
    float4* p = (float4*)(attn + (size_t)row*NL_);
    int t = threadIdx.x;
    int warp = t >> 5, lane = t & 31;
    __shared__ float xw[8];

    float4 v[4];
    float mx = -INFINITY;
    #pragma unroll
    for (int k = 0; k < 4; k++) {
        v[k] = p[t + 256*k];
        mx = fmaxf(mx, fmaxf(fmaxf(v[k].x, v[k].y), fmaxf(v[k].z, v[k].w)));
    }
    mx = warp_max(mx);
    if (lane == 0) xw[warp] = mx;
    __syncthreads();
    {
        float m2 = xw[lane & 7];
        #pragma unroll
        for (int o = 4; o > 0; o >>= 1) m2 = fmaxf(m2, __shfl_xor_sync(0xffffffffu, m2, o));
        mx = m2;
    }
    __syncthreads();

    float sum = 0.f;
    #pragma unroll
    for (int k = 0; k < 4; k++) {
        v[k].x = __expf(v[k].x - mx); v[k].y = __expf(v[k].y - mx);
        v[k].z = __expf(v[k].z - mx); v[k].w = __expf(v[k].w - mx);
        sum += v[k].x + v[k].y + v[k].z + v[k].w;
    }
    sum = warp_sum(sum);
    if (lane == 0) xw[warp] = sum;
    __syncthreads();
    {
        float s2 = xw[lane & 7];
        #pragma unroll
        for (int o = 4; o > 0; o >>= 1) s2 += __shfl_xor_sync(0xffffffffu, s2, o);
        sum = s2;
    }
    float inv = 1.f / sum;
    #pragma unroll
    for (int k = 0; k < 4; k++) {
        v[k].x *= inv; v[k].y *= inv; v[k].z *= inv; v[k].w *= inv;
        p[t + 256*k] = v[k];
    }
}

// ---------------------------------------------------------------- K5: m_h += attn @ logmap0(demo_hyp)
__global__ void __launch_bounds__(256) k5_mh(
    const float* __restrict__ dhyp, const float* __restrict__ attn)
{
    int b = blockIdx.y;
    int chunk = blockIdx.x;               // 64 chunks of 64 x
    int t = threadIdx.x;
    __shared__ __align__(16) float vals[64*DH_];    // 16KB
    __shared__ float scale_s[64];
    int xb = chunk * 64;

    if (t < 64) {
        const float* vp = dhyp + (size_t)(b*NL_ + xb + t)*DH_;
        float n2 = 0.f;
        #pragma unroll
        for (int i = 0; i < DH_; i += 4) {
            float4 q = *(const float4*)(vp + i);
            n2 += q.x*q.x + q.y*q.y + q.z*q.z + q.w*q.w;
        }
        float n = fmaxf(sqrtf(n2), 1e-15f);
        float u = fminf(n, 1.f - 1e-5f);
        scale_s[t] = atanhf(u) / n;
    }
    __syncthreads();

    const float4* src = (const float4*)(dhyp + (size_t)(b*NL_ + xb)*DH_);
    float4* dst = (float4*)vals;
    #pragma unroll
    for (int j = 0; j < 4; j++) {
        int k = t + 256*j;
        float4 q = src[k];
        float s = scale_s[k >> 4];
        q.x *= s; q.y *= s; q.z *= s; q.w *= s;
        dst[k] = q;
    }
    __syncthreads();

    int row   = t & 127;
    int dhalf = t >> 7;
    u64 acc[16];
    #pragma unroll
    for (int i = 0; i < 16; i++) acc[i] = 0;

    const float4* arow = (const float4*)(attn + ((size_t)(b*128 + row)*NL_ + xb));
    #pragma unroll 4
    for (int x4 = 0; x4 < 16; x4++) {
        float4 w = arow[x4];
        #pragma unroll
        for (int xx = 0; xx < 4; xx++) {
            float wv = (&w.x)[xx];
            u64 w2 = pk2(wv, wv);
            const float4* vv = (const float4*)(vals + (x4*4 + xx)*DH_ + dhalf*32);
            #pragma unroll
            for (int i = 0; i < 8; i++) {
                float4 q = vv[i];
                acc[2*i+0] = fma2(pk2(q.x, q.y), w2, acc[2*i+0]);
                acc[2*i+1] = fma2(pk2(q.z, q.w), w2, acc[2*i+1]);
            }
        }
    }
    float* m0 = g_m + (size_t)(b*128 + row)*DH_ + dhalf*32;
    #pragma unroll
    for (int i = 0; i < 16; i++) {
        float lo, hi; upk2(acc[i], lo, hi);
        atomicAdd(m0 + 2*i,     lo);
        atomicAdd(m0 + 2*i + 1, hi);
    }
}

// ---------------------------------------------------------------- K6: hyperbolic epilogue (warp per ba)
__global__ void __launch_bounds__(32) k6_final(float* __restrict__ out)
{
    int ba = blockIdx.x;                  // 64 = b*16+a
    int b = ba >> 4, a = ba & 15;
    int lane = threadIdx.x;               // 32; holds d=lane, d=lane+32

    float g0 = 0.f, g1 = 0.f;
    #pragma unroll 1
    for (int h = 0; h < H_; h++) {
        const float* mp = g_m + (size_t)(b*128 + h*16 + a)*DH_;
        float m0 = mp[lane], m1 = mp[lane+32];
        float nm = fmaxf(sqrtf(warp_sum(m0*m0 + m1*m1)), 1e-15f);
        float th = tanhf(nm) / nm;
        float e0 = th*m0, e1 = th*m1;
        float ne = fmaxf(sqrtf(warp_sum(e0*e0 + e1*e1)), 1e-15f);
        float u = fminf(ne, 1.f - 1e-5f);
        float at = atanhf(u) / ne;
        g0 += at*e0; g1 += at*e1;
    }
    g0 *= (1.f/H_); g1 *= (1.f/H_);
    float ng = fmaxf(sqrtf(warp_sum(g0*g0 + g1*g1)), 1e-15f);
    float th = tanhf(ng) / ng;
    float c0 = th*g0, c1 = th*g1;
    float norm = fmaxf(sqrtf(warp_sum(c0*c0 + c1*c1)), 1e-6f);
    float s = fminf((1.f - 1e-5f) / norm, 1.f) * (1.f/A_);
    atomicAdd(out + b*DH_ + lane,      c0 * s);
    atomicAdd(out + b*DH_ + lane + 32, c1 * s);
}

// ----------------------------------------------------------------
extern "C" void kernel_launch(void* const* d_in, const int* in_sizes, int n_in,
                              void* d_out, int out_size)
{
    const float* curr = (const float*)d_in[0];
    const float* demo = (const float*)d_in[1];
    const float* dhyp = (const float*)d_in[2];
    const int*   mask = (const int*)d_in[3];
    const float* Wq   = (const float*)d_in[4];
    const float* Wk   = (const float*)d_in[5];
    const float* lqw  = (const float*)d_in[6];
    const float* lqb  = (const float*)d_in[7];
    const float* lkw  = (const float*)d_in[8];
    const float* lkb  = (const float*)d_in[9];
    float* out  = (float*)d_out;
    float* attn = out + 256;

    k0_zero<<<128, 256>>>(out);
    k12_prep<<<64, 256>>>(curr, Wq, Wk, lqw, lqb, lkw, lkb);
    dim3 g3(16, 64);
    k3_scores<<<g3, 256>>>(demo, mask, attn);
    k4_softmax<<<512, 256>>>(attn);
    dim3 g5(64, 4);
    k5_mh<<<g5, 256>>>(dhyp, attn);
    k6_final<<<64, 32>>>(out);
}